// round 15
// baseline (speedup 1.0000x reference)
#include <cuda_runtime.h>
#include <cuda_fp16.h>
#include <cstdint>

// Problem constants
#define B_   16
#define C_   128
#define H_   128
#define W_   128
#define OUT_ 256
#define HW_  (H_ * W_)
#define NTILES (B_ * H_ / 2)   // 1024 (b, h-pair) tiles

#define KSTR 136   // halves per Ys row (272 B); conflict-free ldmatrix rows

// Shared memory layout (bytes):
//  [0      : 34816)   Ys0  half[128][136]
//  [34816  : 69632)   Ys1  half[128][136]
//  [69632  : 135168)  A fragments (fp16 packed), 64 KB
#define SMEM_YS   34816
#define SMEM_A    (2 * SMEM_YS)              // 69632
#define SMEM_TOT  (SMEM_A + 65536)           // 135168

__device__ __forceinline__ uint32_t s2u(const void* p) {
    uint32_t a;
    asm("{ .reg .u64 t; cvta.to.shared.u64 t, %1; cvt.u32.u64 %0, t; }" : "=r"(a) : "l"(p));
    return a;
}

__device__ __forceinline__ void mma_f16(float* d, const uint32_t* a, const uint32_t* b) {
    asm volatile(
        "mma.sync.aligned.m16n8k16.row.col.f32.f16.f16.f32 "
        "{%0,%1,%2,%3}, {%4,%5,%6,%7}, {%8,%9}, {%0,%1,%2,%3};"
        : "+f"(d[0]), "+f"(d[1]), "+f"(d[2]), "+f"(d[3])
        : "r"(a[0]), "r"(a[1]), "r"(a[2]), "r"(a[3]), "r"(b[0]), "r"(b[1]));
}

// ---------------------------------------------------------------------------
// Persistent fused kernel (R13 structure):
//   Prologue: pack W into fp16 A-fragment image in smem (once per SM).
//   Per tile: merged depthwise (rows h0,h0+1) -> Ys0/Ys1;
//             L2 prefetch of NEXT tile's x rows (lands under the GEMMs);
//             per row fp16 GEMM m16n8k16 + SHUFFLE-TRANSPOSE epilogue
//             (quad 4x4 transpose -> two STG.128 per lane; no smem stage).
// ---------------------------------------------------------------------------
__global__ __launch_bounds__(512, 1) void fused_kernel(
    const float* __restrict__ x,
    const float* __restrict__ colk,
    const float* __restrict__ rowk,
    const float* __restrict__ Wg,
    float* __restrict__ out)
{
    extern __shared__ char smem[];
    const uint32_t sb = s2u(smem);
    const unsigned FULL = 0xFFFFFFFFu;

    const int tid  = threadIdx.x;
    const int lane = tid & 31;
    const int warp = tid >> 5;

    // ---------------- Prologue: pack W into smem A image (once per SM) -------
    {
        #pragma unroll
        for (int i = 0; i < 8; ++i) {
            const int idx4  = tid + i * 512;        // uint4 index, 0..4095
            const int l     = idx4 & 31;
            const int mtile = (idx4 >> 5) & 15;
            const int kstep = idx4 >> 9;
            uint32_t vals[4];
            #pragma unroll
            for (int r = 0; r < 4; ++r) {
                const int m = mtile * 16 + (l >> 2) + ((r & 1) << 3);
                const int k = kstep * 16 + ((l & 3) << 1) + ((r >> 1) << 3);
                const float2 w2 = *(const float2*)(Wg + (size_t)m * C_ + k);
                const __half2 h = __floats2half2_rn(w2.x, w2.y);
                vals[r] = *(const uint32_t*)&h;
            }
            *(uint4*)(smem + SMEM_A + (size_t)idx4 * 16) =
                make_uint4(vals[0], vals[1], vals[2], vals[3]);
        }
    }
    __syncthreads();

    const int wm = warp >> 2;   // 0..3
    const int wn = warp & 3;    // 0..3
    const uint32_t aBase = sb + SMEM_A + (uint32_t)(((wm * 4) * 32 + lane) * 16);
    const int bt   = lane >> 3;
    const int brow = lane & 7;
    const int qa   = lane & 3;
    const int qr   = lane >> 2;

    // ---------------- Persistent tile loop ----------------
    for (int t = blockIdx.x; t < NTILES; t += gridDim.x) {
        const int b  = t >> 6;          // 64 h-pairs per batch
        const int h0 = (t & 63) * 2;

        // ---- Phase 1: merged depthwise (rows h0, h0+1) -> Ys0, Ys1 ----
        {
            #pragma unroll
            for (int i = 0; i < 8; ++i) {
                const int c = warp * 8 + i;
                const float r0 = rowk[c * 3 + 0], r1 = rowk[c * 3 + 1], r2 = rowk[c * 3 + 2];
                const float ck0 = colk[c * 3 + 0], ck1 = colk[c * 3 + 1], ck2 = colk[c * 3 + 2];
                const float* xc = x + ((size_t)(b * C_ + c) * H_) * W_;

                float tt[4][4];
                #pragma unroll
                for (int j = 0; j < 4; ++j) {
                    const int row = h0 - 1 + j;
                    float4 v = make_float4(0.f, 0.f, 0.f, 0.f);
                    if (row >= 0 && row < H_)
                        v = *(const float4*)(xc + (size_t)row * W_ + lane * 4);
                    float left  = __shfl_up_sync(FULL, v.w, 1);
                    float right = __shfl_down_sync(FULL, v.x, 1);
                    if (lane == 0)  left = 0.f;
                    if (lane == 31) right = 0.f;
                    tt[j][0] = r0 * left + r1 * v.x + r2 * v.y;
                    tt[j][1] = r0 * v.x  + r1 * v.y + r2 * v.z;
                    tt[j][2] = r0 * v.y  + r1 * v.z + r2 * v.w;
                    tt[j][3] = r0 * v.z  + r1 * v.w + r2 * right;
                }
                #pragma unroll
                for (int row = 0; row < 2; ++row) {
                    float y0 = ck0 * tt[row][0] + ck1 * tt[row + 1][0] + ck2 * tt[row + 2][0];
                    float y1 = ck0 * tt[row][1] + ck1 * tt[row + 1][1] + ck2 * tt[row + 2][1];
                    float y2 = ck0 * tt[row][2] + ck1 * tt[row + 1][2] + ck2 * tt[row + 2][2];
                    float y3 = ck0 * tt[row][3] + ck1 * tt[row + 1][3] + ck2 * tt[row + 2][3];
                    const __half2 h01 = __floats2half2_rn(y0, y1);
                    const __half2 h23 = __floats2half2_rn(y2, y3);
                    uint2 tw;
                    tw.x = *(const uint32_t*)&h01;
                    tw.y = *(const uint32_t*)&h23;
                    *(uint2*)(smem + row * SMEM_YS + (size_t)c * (KSTR * 2) + lane * 8) = tw;
                }
            }
        }

        // ---- L2 prefetch of the NEXT tile's x rows (lands during the GEMMs) ----
        {
            const int tn = t + gridDim.x;
            if (tn < NTILES) {
                const int bn  = tn >> 6;
                const int h0n = (tn & 63) * 2;
                #pragma unroll
                for (int j = 0; j < 4; ++j) {
                    const int l  = tid + j * 512;      // 0..2047 lines
                    const int c  = l >> 4;
                    const int rj = (l >> 2) & 3;
                    const int q  = l & 3;
                    const int row = h0n - 1 + rj;
                    if (row >= 0 && row < H_) {
                        const float* pp = x + ((size_t)(bn * C_ + c) * H_ + row) * W_ + q * 32;
                        asm volatile("prefetch.global.L2 [%0];" :: "l"(pp));
                    }
                }
            }
        }
        __syncthreads();                 // Ys visible to all warps

        // ---- Phase 2: per-row GEMM + shuffle-transpose epilogue ----
        #pragma unroll 1
        for (int row = 0; row < 2; ++row) {
            const uint32_t ysBase = sb + row * SMEM_YS;

            float acc[4][4][4] = {};
            #pragma unroll
            for (int k = 0; k < 8; ++k) {
                uint32_t a[4][4];
                #pragma unroll
                for (int mt = 0; mt < 4; ++mt) {
                    const uint32_t addr = aBase + (uint32_t)(k * 16 * 512 + mt * 512);
                    asm volatile("ld.shared.v4.b32 {%0,%1,%2,%3}, [%4];"
                                 : "=r"(a[mt][0]), "=r"(a[mt][1]),
                                   "=r"(a[mt][2]), "=r"(a[mt][3])
                                 : "r"(addr));
                }
                uint32_t bf[4][2];
                #pragma unroll
                for (int q = 0; q < 2; ++q) {
                    const int krow = k * 16 + (bt & 1) * 8 + brow;
                    const int col  = wn * 32 + q * 16 + (bt >> 1) * 8;
                    const uint32_t addr = ysBase + (uint32_t)(krow * (KSTR * 2) + col * 2);
                    asm volatile("ldmatrix.sync.aligned.m8n8.x4.trans.shared.b16 "
                                 "{%0,%1,%2,%3}, [%4];"
                                 : "=r"(bf[q * 2][0]), "=r"(bf[q * 2][1]),
                                   "=r"(bf[q * 2 + 1][0]), "=r"(bf[q * 2 + 1][1])
                                 : "r"(addr));
                }
                #pragma unroll
                for (int mt = 0; mt < 4; ++mt)
                    #pragma unroll
                    for (int nt = 0; nt < 4; ++nt)
                        mma_f16(acc[mt][nt], a[mt], bf[nt]);
            }

            // Shuffle-transpose epilogue:
            // quad 4x4 transpose over nt -> lane qa holds cols 8*qa..8*qa+7
            // of output row (wm*64 + mt*16 + hf*8 + qr); two STG.128 per lane.
            float* ob = out + ((size_t)b * OUT_) * HW_ + (size_t)(h0 + row) * W_ + wn * 32;
            #pragma unroll
            for (int mt = 0; mt < 4; ++mt) {
                #pragma unroll
                for (int hf = 0; hf < 2; ++hf) {
                    float2 v0 = make_float2(acc[mt][0][2 * hf], acc[mt][0][2 * hf + 1]);
                    float2 v1 = make_float2(acc[mt][1][2 * hf], acc[mt][1][2 * hf + 1]);
                    float2 v2 = make_float2(acc[mt][2][2 * hf], acc[mt][2][2 * hf + 1]);
                    float2 v3 = make_float2(acc[mt][3][2 * hf], acc[mt][3][2 * hf + 1]);
                    // round 1: swap bit0(lane) with bit0(slot)
                    float2 x0 = (qa & 1) ? v0 : v1;
                    float2 x1 = (qa & 1) ? v2 : v3;
                    x0.x = __shfl_xor_sync(FULL, x0.x, 1);
                    x0.y = __shfl_xor_sync(FULL, x0.y, 1);
                    x1.x = __shfl_xor_sync(FULL, x1.x, 1);
                    x1.y = __shfl_xor_sync(FULL, x1.y, 1);
                    if (qa & 1) { v0 = x0; v2 = x1; } else { v1 = x0; v3 = x1; }
                    // round 2: swap bit1(lane) with bit1(slot)
                    float2 y0 = (qa & 2) ? v0 : v2;
                    float2 y1 = (qa & 2) ? v1 : v3;
                    y0.x = __shfl_xor_sync(FULL, y0.x, 2);
                    y0.y = __shfl_xor_sync(FULL, y0.y, 2);
                    y1.x = __shfl_xor_sync(FULL, y1.x, 2);
                    y1.y = __shfl_xor_sync(FULL, y1.y, 2);
                    if (qa & 2) { v0 = y0; v1 = y1; } else { v2 = y0; v3 = y1; }
                    // store: lane qa owns cols 8*qa .. 8*qa+7 of row o
                    const int o = wm * 64 + mt * 16 + hf * 8 + qr;
                    float* orow = ob + (size_t)o * HW_ + qa * 8;
                    *(float4*)orow       = make_float4(v0.x, v0.y, v1.x, v1.y);
                    *(float4*)(orow + 4) = make_float4(v2.x, v2.y, v3.x, v3.y);
                }
            }
        }
        __syncthreads();                 // GEMM reads done before next tile's dw
    }
}

// ---------------------------------------------------------------------------
extern "C" void kernel_launch(void* const* d_in, const int* in_sizes, int n_in,
                              void* d_out, int out_size)
{
    (void)in_sizes; (void)n_in; (void)out_size;
    const float* x    = (const float*)d_in[0];
    const float* colk = (const float*)d_in[1];
    const float* rowk = (const float*)d_in[2];
    const float* pw   = (const float*)d_in[3];
    float* out = (float*)d_out;

    int nsm = 0;
    cudaDeviceGetAttribute(&nsm, cudaDevAttrMultiProcessorCount, 0);
    if (nsm <= 0) nsm = 148;
    int grid = nsm < NTILES ? nsm : NTILES;

    cudaFuncSetAttribute(fused_kernel, cudaFuncAttributeMaxDynamicSharedMemorySize, SMEM_TOT);
    fused_kernel<<<grid, 512, SMEM_TOT>>>(x, colk, rowk, pw, out);
}

// round 16
// speedup vs baseline: 1.1284x; 1.1284x over previous
#include <cuda_runtime.h>
#include <cuda_fp16.h>
#include <cstdint>

// Problem constants
#define B_   16
#define C_   128
#define H_   128
#define W_   128
#define OUT_ 256
#define HW_  (H_ * W_)
#define NTILES (B_ * H_ / 2)   // 1024 (b, h-pair) tiles

#define KSTR 136   // halves per Ys row (272 B); conflict-free ldmatrix rows

// Shared memory layout (bytes)  (172 KB -> leaves 56 KB L1D carveout):
//  [0      : 34816)   Ys0  half[128][136]
//  [34816  : 69632)   Ys1  half[128][136]
//  [69632  : 135168)  A fragments (fp16 packed), 64 KB
//  [135168 : 172032)  per-warp store stage: 16 warps x (16 x 36 floats)
#define SMEM_YS   34816
#define SMEM_A    (2 * SMEM_YS)              // 69632
#define SMEM_STG  (SMEM_A + 65536)           // 135168
#define DSTR      36                          // 144 B stage row stride (16B-aligned)
#define STG_WORDS (16 * DSTR)                 // 576 floats / warp
#define SMEM_TOT  (SMEM_STG + 16 * STG_WORDS * 4)   // 172032

__device__ __forceinline__ uint32_t s2u(const void* p) {
    uint32_t a;
    asm("{ .reg .u64 t; cvta.to.shared.u64 t, %1; cvt.u32.u64 %0, t; }" : "=r"(a) : "l"(p));
    return a;
}

__device__ __forceinline__ void mma_f16(float* d, const uint32_t* a, const uint32_t* b) {
    asm volatile(
        "mma.sync.aligned.m16n8k16.row.col.f32.f16.f16.f32 "
        "{%0,%1,%2,%3}, {%4,%5,%6,%7}, {%8,%9}, {%0,%1,%2,%3};"
        : "+f"(d[0]), "+f"(d[1]), "+f"(d[2]), "+f"(d[3])
        : "r"(a[0]), "r"(a[1]), "r"(a[2]), "r"(a[3]), "r"(b[0]), "r"(b[1]));
}

// ---------------------------------------------------------------------------
// Persistent fused kernel (R13 structure + streaming output stores):
//   Prologue: pack W into fp16 A-fragment image in smem (once per SM).
//   Per tile: merged depthwise (rows h0,h0+1) -> Ys0/Ys1;
//             L2 prefetch of NEXT tile's x rows (lands under the GEMMs);
//             per row fp16 GEMM m16n8k16 + per-warp staged coalesced epilogue
//             with st.global.cs (evict-first: out is write-once, keep L2 for x).
// ---------------------------------------------------------------------------
__global__ __launch_bounds__(512, 1) void fused_kernel(
    const float* __restrict__ x,
    const float* __restrict__ colk,
    const float* __restrict__ rowk,
    const float* __restrict__ Wg,
    float* __restrict__ out)
{
    extern __shared__ char smem[];
    const uint32_t sb = s2u(smem);

    const int tid  = threadIdx.x;
    const int lane = tid & 31;
    const int warp = tid >> 5;

    // ---------------- Prologue: pack W into smem A image (once per SM) -------
    {
        #pragma unroll
        for (int i = 0; i < 8; ++i) {
            const int idx4  = tid + i * 512;        // uint4 index, 0..4095
            const int l     = idx4 & 31;
            const int mtile = (idx4 >> 5) & 15;
            const int kstep = idx4 >> 9;
            uint32_t vals[4];
            #pragma unroll
            for (int r = 0; r < 4; ++r) {
                const int m = mtile * 16 + (l >> 2) + ((r & 1) << 3);
                const int k = kstep * 16 + ((l & 3) << 1) + ((r >> 1) << 3);
                const float2 w2 = *(const float2*)(Wg + (size_t)m * C_ + k);
                const __half2 h = __floats2half2_rn(w2.x, w2.y);
                vals[r] = *(const uint32_t*)&h;
            }
            *(uint4*)(smem + SMEM_A + (size_t)idx4 * 16) =
                make_uint4(vals[0], vals[1], vals[2], vals[3]);
        }
    }
    __syncthreads();

    const int wm = warp >> 2;   // 0..3
    const int wn = warp & 3;    // 0..3
    const uint32_t aBase = sb + SMEM_A + (uint32_t)(((wm * 4) * 32 + lane) * 16);
    const int bt   = lane >> 3;
    const int brow = lane & 7;
    float* stage = (float*)(smem + SMEM_STG) + warp * STG_WORDS;

    // ---------------- Persistent tile loop ----------------
    for (int t = blockIdx.x; t < NTILES; t += gridDim.x) {
        const int b  = t >> 6;          // 64 h-pairs per batch
        const int h0 = (t & 63) * 2;

        // ---- Phase 1: merged depthwise (rows h0, h0+1) -> Ys0, Ys1 ----
        {
            const unsigned FULL = 0xFFFFFFFFu;
            #pragma unroll
            for (int i = 0; i < 8; ++i) {
                const int c = warp * 8 + i;
                const float r0 = rowk[c * 3 + 0], r1 = rowk[c * 3 + 1], r2 = rowk[c * 3 + 2];
                const float ck0 = colk[c * 3 + 0], ck1 = colk[c * 3 + 1], ck2 = colk[c * 3 + 2];
                const float* xc = x + ((size_t)(b * C_ + c) * H_) * W_;

                float tt[4][4];
                #pragma unroll
                for (int j = 0; j < 4; ++j) {
                    const int row = h0 - 1 + j;
                    float4 v = make_float4(0.f, 0.f, 0.f, 0.f);
                    if (row >= 0 && row < H_)
                        v = *(const float4*)(xc + (size_t)row * W_ + lane * 4);
                    float left  = __shfl_up_sync(FULL, v.w, 1);
                    float right = __shfl_down_sync(FULL, v.x, 1);
                    if (lane == 0)  left = 0.f;
                    if (lane == 31) right = 0.f;
                    tt[j][0] = r0 * left + r1 * v.x + r2 * v.y;
                    tt[j][1] = r0 * v.x  + r1 * v.y + r2 * v.z;
                    tt[j][2] = r0 * v.y  + r1 * v.z + r2 * v.w;
                    tt[j][3] = r0 * v.z  + r1 * v.w + r2 * right;
                }
                #pragma unroll
                for (int row = 0; row < 2; ++row) {
                    float y0 = ck0 * tt[row][0] + ck1 * tt[row + 1][0] + ck2 * tt[row + 2][0];
                    float y1 = ck0 * tt[row][1] + ck1 * tt[row + 1][1] + ck2 * tt[row + 2][1];
                    float y2 = ck0 * tt[row][2] + ck1 * tt[row + 1][2] + ck2 * tt[row + 2][2];
                    float y3 = ck0 * tt[row][3] + ck1 * tt[row + 1][3] + ck2 * tt[row + 2][3];
                    const __half2 h01 = __floats2half2_rn(y0, y1);
                    const __half2 h23 = __floats2half2_rn(y2, y3);
                    uint2 tw;
                    tw.x = *(const uint32_t*)&h01;
                    tw.y = *(const uint32_t*)&h23;
                    *(uint2*)(smem + row * SMEM_YS + (size_t)c * (KSTR * 2) + lane * 8) = tw;
                }
            }
        }

        // ---- L2 prefetch of the NEXT tile's x rows (lands during the GEMMs) ----
        {
            const int tn = t + gridDim.x;
            if (tn < NTILES) {
                const int bn  = tn >> 6;
                const int h0n = (tn & 63) * 2;
                #pragma unroll
                for (int j = 0; j < 4; ++j) {
                    const int l  = tid + j * 512;      // 0..2047 lines
                    const int c  = l >> 4;
                    const int rj = (l >> 2) & 3;
                    const int q  = l & 3;
                    const int row = h0n - 1 + rj;
                    if (row >= 0 && row < H_) {
                        const float* pp = x + ((size_t)(bn * C_ + c) * H_ + row) * W_ + q * 32;
                        asm volatile("prefetch.global.L2 [%0];" :: "l"(pp));
                    }
                }
            }
        }
        __syncthreads();                 // Ys visible to all warps

        // ---- Phase 2: per-row GEMM + per-warp staged epilogue ----
        #pragma unroll 1
        for (int row = 0; row < 2; ++row) {
            const uint32_t ysBase = sb + row * SMEM_YS;

            float acc[4][4][4] = {};
            #pragma unroll
            for (int k = 0; k < 8; ++k) {
                uint32_t a[4][4];
                #pragma unroll
                for (int mt = 0; mt < 4; ++mt) {
                    const uint32_t addr = aBase + (uint32_t)(k * 16 * 512 + mt * 512);
                    asm volatile("ld.shared.v4.b32 {%0,%1,%2,%3}, [%4];"
                                 : "=r"(a[mt][0]), "=r"(a[mt][1]),
                                   "=r"(a[mt][2]), "=r"(a[mt][3])
                                 : "r"(addr));
                }
                uint32_t bf[4][2];
                #pragma unroll
                for (int q = 0; q < 2; ++q) {
                    const int krow = k * 16 + (bt & 1) * 8 + brow;
                    const int col  = wn * 32 + q * 16 + (bt >> 1) * 8;
                    const uint32_t addr = ysBase + (uint32_t)(krow * (KSTR * 2) + col * 2);
                    asm volatile("ldmatrix.sync.aligned.m8n8.x4.trans.shared.b16 "
                                 "{%0,%1,%2,%3}, [%4];"
                                 : "=r"(bf[q * 2][0]), "=r"(bf[q * 2][1]),
                                   "=r"(bf[q * 2 + 1][0]), "=r"(bf[q * 2 + 1][1])
                                 : "r"(addr));
                }
                #pragma unroll
                for (int mt = 0; mt < 4; ++mt)
                    #pragma unroll
                    for (int nt = 0; nt < 4; ++nt)
                        mma_f16(acc[mt][nt], a[mt], bf[nt]);
            }

            float* ob = out + ((size_t)b * OUT_) * HW_ + (size_t)(h0 + row) * W_ + wn * 32;
            #pragma unroll
            for (int mt = 0; mt < 4; ++mt) {
                __syncwarp();
                #pragma unroll
                for (int nt = 0; nt < 4; ++nt) {
                    const int p  = nt * 8 + (lane & 3) * 2;
                    const int dr = lane >> 2;
                    *(float2*)&stage[dr * DSTR + p] =
                        make_float2(acc[mt][nt][0], acc[mt][nt][1]);
                    *(float2*)&stage[(dr + 8) * DSTR + p] =
                        make_float2(acc[mt][nt][2], acc[mt][nt][3]);
                }
                __syncwarp();
                #pragma unroll
                for (int rr = 0; rr < 4; ++rr) {
                    const int r4   = rr * 4 + (lane >> 3);       // 0..15
                    const int colf = (lane & 7) * 4;
                    const float4 v = *(const float4*)&stage[r4 * DSTR + colf];
                    const int o = wm * 64 + mt * 16 + r4;
                    // streaming store: out is write-once; keep L2 for x prefetch
                    __stcs((float4*)(ob + (size_t)o * HW_ + colf), v);
                }
            }
        }
        __syncthreads();                 // GEMM reads done before next tile's dw
    }
}

// ---------------------------------------------------------------------------
extern "C" void kernel_launch(void* const* d_in, const int* in_sizes, int n_in,
                              void* d_out, int out_size)
{
    (void)in_sizes; (void)n_in; (void)out_size;
    const float* x    = (const float*)d_in[0];
    const float* colk = (const float*)d_in[1];
    const float* rowk = (const float*)d_in[2];
    const float* pw   = (const float*)d_in[3];
    float* out = (float*)d_out;

    int nsm = 0;
    cudaDeviceGetAttribute(&nsm, cudaDevAttrMultiProcessorCount, 0);
    if (nsm <= 0) nsm = 148;
    int grid = nsm < NTILES ? nsm : NTILES;

    cudaFuncSetAttribute(fused_kernel, cudaFuncAttributeMaxDynamicSharedMemorySize, SMEM_TOT);
    fused_kernel<<<grid, 512, SMEM_TOT>>>(x, colk, rowk, pw, out);
}